// round 11
// baseline (speedup 1.0000x reference)
#include <cuda_runtime.h>
#include <cuda_bf16.h>

#define HH 384
#define WW 384
#define BATCH 4
#define CIN 64
#define COUT 64
#define NPIX (BATCH*HH*WW)

// packed fp32x2 FMA (sm_103a; ptxas never auto-fuses this from C++)
#define FMA2(d, a, b, c) \
    asm("fma.rn.f32x2 %0, %1, %2, %3;" : "=l"(d) : "l"(a), "l"(b), "l"(c))

// Scratch: combined weights + per-pixel route flags.
// g_wcomb layout: [ci][tap][co*2 + path], path 0 = W_low_eff, path 1 = W_high - W_low_eff
__device__ float g_wcomb[64 * 9 * 128];
__device__ unsigned char g_flags[NPIX];

// ---------------------------------------------------------------------------
// Prep 1: compose low-rank path into a single 3x3 kernel; interleave (L, D).
// ---------------------------------------------------------------------------
__global__ void prep_weights(const float* __restrict__ high_w,   // (64,64,3,3)
                             const float* __restrict__ low1_w,   // (16,64,3,3)
                             const float* __restrict__ low2_w)   // (64,16,1,1)
{
    int id = blockIdx.x * blockDim.x + threadIdx.x;
    if (id >= 64 * 64 * 9) return;
    int co  = id / 576;
    int rem = id % 576;
    int ci  = rem / 9;
    int tap = rem % 9;
    float wle = 0.0f;
#pragma unroll
    for (int m = 0; m < 16; m++)
        wle += low2_w[co * 16 + m] * low1_w[(m * 64 + ci) * 9 + tap];
    float wh = high_w[(co * 64 + ci) * 9 + tap];
    int base = (ci * 9 + tap) * 128 + co * 2;
    g_wcomb[base + 0] = wle;        // low path  (lo lane)
    g_wcomb[base + 1] = wh - wle;   // delta     (hi lane)
}

// ---------------------------------------------------------------------------
// Prep 2: route flags (mask/inv partition covers all N pixels exactly once).
// ---------------------------------------------------------------------------
__global__ void prep_flags(const int* __restrict__ mask_idx,
                           const int* __restrict__ inv_idx)
{
    int i = blockIdx.x * blockDim.x + threadIdx.x;
    if (i >= NPIX) return;
    if (i < NPIX / 2) g_flags[mask_idx[i]] = 1;
    else              g_flags[inv_idx[i - NPIX / 2]] = 0;
}

// ---------------------------------------------------------------------------
// Main conv: 8x8 pixel tile per block, 256 threads.
// thread = 16 pixel-groups (4 consecutive-w pixels) x 16 cout-groups (4 couts).
// Accumulators are (L, D) packed f32x2 pairs -> 16 x 64-bit accs / thread.
// x tile staged PRE-DUPLICATED (v,v) so the packed multiplier is one LDS.64.
// ---------------------------------------------------------------------------
__global__ __launch_bounds__(256)
void conv_main(const float* __restrict__ x, float* __restrict__ out)
{
    __shared__ float2 xs2[8][10][13];                   // (v,v) pairs, padded rows
    __shared__ __align__(16) float ws[8 * 9 * 128];     // [ci][tap][co*2+path]

    const int b  = blockIdx.z;
    const int h0 = blockIdx.y * 8;
    const int w0 = blockIdx.x * 8;
    const int tid = threadIdx.x;
    const int pg = tid & 15;        // pixel group
    const int cg = tid >> 4;        // cout group (4 real couts)
    const int r  = pg >> 1;         // tile row 0..7
    const int c4 = (pg & 1) * 4;    // tile col base 0 or 4

    unsigned long long acc[4][4];
#pragma unroll
    for (int p = 0; p < 4; p++)
#pragma unroll
        for (int j = 0; j < 4; j++) acc[p][j] = 0ull;

    for (int ci0 = 0; ci0 < 64; ci0 += 8) {
        // stage weight slice (9216 floats, contiguous) via float4
        {
            const float4* src = (const float4*)(g_wcomb + ci0 * 9 * 128);
            float4* dst = (float4*)ws;
#pragma unroll
            for (int i = 0; i < 9; i++)
                dst[tid + i * 256] = src[tid + i * 256];
        }
        // stage x halo tile: 8 ci x 10 x 10 (zero-padded SAME borders), duplicated
        for (int i = tid; i < 800; i += 256) {
            int ci = i / 100;
            int rr = (i % 100) / 10;
            int cc = i % 10;
            int gh = h0 + rr - 1;
            int gw = w0 + cc - 1;
            float v = 0.0f;
            if (gh >= 0 && gh < HH && gw >= 0 && gw < WW)
                v = x[((b * CIN + ci0 + ci) * HH + gh) * WW + gw];
            xs2[ci][rr][cc] = make_float2(v, v);
        }
        __syncthreads();

        for (int ci = 0; ci < 8; ci++) {
#pragma unroll
            for (int kh = 0; kh < 3; kh++) {
                unsigned long long xv2[6];
#pragma unroll
                for (int i = 0; i < 6; i++)
                    xv2[i] = *(const unsigned long long*)&xs2[ci][r + kh][c4 + i];
#pragma unroll
                for (int kw = 0; kw < 3; kw++) {
                    const ulonglong2* wp =
                        (const ulonglong2*)&ws[((ci * 3 + kh) * 3 + kw) * 128 + cg * 8];
                    ulonglong2 wA = wp[0];   // pairs (co0: L,D) (co1: L,D)
                    ulonglong2 wB = wp[1];   // pairs (co2)      (co3)
#pragma unroll
                    for (int p = 0; p < 4; p++) {
                        unsigned long long xp = xv2[p + kw];
                        FMA2(acc[p][0], wA.x, xp, acc[p][0]);
                        FMA2(acc[p][1], wA.y, xp, acc[p][1]);
                        FMA2(acc[p][2], wB.x, xp, acc[p][2]);
                        FMA2(acc[p][3], wB.y, xp, acc[p][3]);
                    }
                }
            }
        }
        __syncthreads();
    }

    // epilogue: out = L + flag * D  (lo lane = low path, hi lane = delta)
    const int hh = h0 + r;
#pragma unroll
    for (int p = 0; p < 4; p++) {
        int wcol = w0 + c4 + p;
        int n = (b * HH + hh) * WW + wcol;
        float sel = g_flags[n] ? 1.0f : 0.0f;
#pragma unroll
        for (int j = 0; j < 4; j++) {
            int co = cg * 4 + j;
            unsigned long long v = acc[p][j];
            float L = __uint_as_float((unsigned int)v);
            float D = __uint_as_float((unsigned int)(v >> 32));
            out[((b * COUT + co) * HH + hh) * WW + wcol] = fmaf(sel, D, L);
        }
    }
}

// ---------------------------------------------------------------------------
extern "C" void kernel_launch(void* const* d_in, const int* in_sizes, int n_in,
                              void* d_out, int out_size)
{
    const float* x      = (const float*)d_in[0];
    const float* high_w = (const float*)d_in[1];
    const float* low1_w = (const float*)d_in[2];
    const float* low2_w = (const float*)d_in[3];
    const int* mask_idx = (const int*)d_in[4];
    const int* inv_idx  = (const int*)d_in[5];
    float* out = (float*)d_out;

    prep_weights<<<(64 * 64 * 9 + 255) / 256, 256>>>(high_w, low1_w, low2_w);
    prep_flags<<<(NPIX + 255) / 256, 256>>>(mask_idx, inv_idx);

    dim3 grid(WW / 8, HH / 8, BATCH);   // 48 x 48 x 4 = 9216 blocks
    conv_main<<<grid, 256>>>(x, out);
}

// round 13
// speedup vs baseline: 2.2244x; 2.2244x over previous
#include <cuda_runtime.h>
#include <cuda_bf16.h>
#include <cstdint>

#define HH 384
#define WW 384
#define BATCH 4
#define CIN 64
#define COUT 64
#define NPIX (BATCH*HH*WW)

// ---------------------------------------------------------------------------
// Scratch: A operand pre-baked in mma.m16n8k8 fragment order, tf32-rounded.
// Layout: g_amma[((tap*8 + kc)*8 + ct)*128 + lane*4 + j]
//   j: a0..a3 of the fragment; virtual row v = ct*16 + (lane>>2) + 8*(j&1)
//   ci = kc*8 + (lane&3) + 4*(j>>1)
//   rows v<64: W_low_eff(co=v), rows v>=64: W_high(co=v-64)
// ---------------------------------------------------------------------------
__device__ float g_amma[9 * 8192];
__device__ unsigned char g_flags[NPIX];

__device__ __forceinline__ float tf32_round(float v) {
    uint32_t t;
    asm("cvt.rna.tf32.f32 %0, %1;" : "=r"(t) : "f"(v));
    return __uint_as_float(t);
}

__device__ __forceinline__ void mma_tf32(float* d, const uint32_t* a,
                                         const uint32_t* b) {
    asm volatile(
        "mma.sync.aligned.m16n8k8.row.col.f32.tf32.tf32.f32 "
        "{%0,%1,%2,%3}, {%4,%5,%6,%7}, {%8,%9}, {%0,%1,%2,%3};"
        : "+f"(d[0]), "+f"(d[1]), "+f"(d[2]), "+f"(d[3])
        : "r"(a[0]), "r"(a[1]), "r"(a[2]), "r"(a[3]), "r"(b[0]), "r"(b[1]));
}

// ---------------------------------------------------------------------------
// Prep 1: weights -> fragment-ordered, tf32-rounded A images.
// ---------------------------------------------------------------------------
__global__ void prep_weights_mma(const float* __restrict__ high_w,  // (64,64,3,3)
                                 const float* __restrict__ low1_w,  // (16,64,3,3)
                                 const float* __restrict__ low2_w)  // (64,16,1,1)
{
    int id = blockIdx.x * blockDim.x + threadIdx.x;
    if (id >= 9 * 8192) return;
    int j    = id & 3;
    int lane = (id >> 2) & 31;
    int ct   = (id >> 7) & 7;
    int kc   = (id >> 10) & 7;
    int tap  = id >> 13;
    int v  = ct * 16 + (lane >> 2) + 8 * (j & 1);
    int ci = kc * 8 + (lane & 3) + 4 * (j >> 1);
    float val;
    if (v < 64) {
        float wle = 0.0f;
#pragma unroll
        for (int m = 0; m < 16; m++)
            wle += low2_w[v * 16 + m] * low1_w[(m * 64 + ci) * 9 + tap];
        val = wle;
    } else {
        val = high_w[((v - 64) * 64 + ci) * 9 + tap];
    }
    g_amma[id] = tf32_round(val);
}

// ---------------------------------------------------------------------------
// Prep 2: route flags (mask/inv partition covers all N pixels exactly once).
// ---------------------------------------------------------------------------
__global__ void prep_flags(const int* __restrict__ mask_idx,
                           const int* __restrict__ inv_idx)
{
    int i = blockIdx.x * blockDim.x + threadIdx.x;
    if (i >= NPIX) return;
    if (i < NPIX / 2) g_flags[mask_idx[i]] = 1;
    else              g_flags[inv_idx[i - NPIX / 2]] = 0;
}

// ---------------------------------------------------------------------------
// Main: 128-pixel strip x 128 virtual couts per CTA via mma.sync tf32.
// 256 threads = 8 warps; warp w owns pixels [w*16, w*16+16).
// smem: [flags 128B][A tap slice 32KB][x row cache 64x132 fp32 33792B]
// ---------------------------------------------------------------------------
#define OFF_FLAGS 0
#define OFF_A     128
#define OFF_CACHE (128 + 32768)
#define SMEM_TOTAL (OFF_CACHE + 64*132*4)   // 66688 B

__global__ __launch_bounds__(256)
void conv_mma(const float* __restrict__ x, float* __restrict__ out)
{
    extern __shared__ char smem[];
    unsigned char* flg = (unsigned char*)(smem + OFF_FLAGS);
    float4* As   = (float4*)(smem + OFF_A);
    float* cache = (float*)(smem + OFF_CACHE);          // [64][132] tf32-rounded

    const int tid  = threadIdx.x;
    const int w    = tid >> 5;       // warp 0..7
    const int lane = tid & 31;

    const int idx = blockIdx.x;
    const int b   = idx / 1152;
    const int rem = idx % 1152;
    const int h   = rem / 3;
    const int w0  = (rem % 3) * 128;

    if (tid < 128) flg[tid] = g_flags[(b * HH + h) * WW + w0 + tid];

    float d[8][2][4];
#pragma unroll
    for (int ct = 0; ct < 8; ct++)
#pragma unroll
        for (int nt = 0; nt < 2; nt++)
#pragma unroll
            for (int i = 0; i < 4; i++) d[ct][nt][i] = 0.0f;

    for (int kh = 0; kh < 3; kh++) {
        __syncthreads();            // prior tap's reads of cache/A done
        // stage x row (64 ci x 130 valid cols), tf32-rounded once
        const int rin = h + kh - 1;
        for (int i = tid; i < 64 * 132; i += 256) {
            int ci = i / 132, cc = i % 132;
            int g = w0 - 1 + cc;
            float v = 0.0f;
            if (rin >= 0 && rin < HH && g >= 0 && g < WW && cc < 130)
                v = x[((b * CIN + ci) * HH + rin) * WW + g];
            cache[i] = tf32_round(v);
        }
        __syncthreads();

        for (int kw = 0; kw < 3; kw++) {
            const int tap = kh * 3 + kw;
            if (kw) __syncthreads();            // A buffer reuse
            // stage A tap slice: 8192 floats = 2048 float4
            {
                const float4* src = (const float4*)(g_amma + tap * 8192);
#pragma unroll
                for (int i = 0; i < 8; i++)
                    As[tid + i * 256] = src[tid + i * 256];
            }
            __syncthreads();

            const int nb0 = w * 16 + (lane >> 2) + kw;  // cache col, nt=0
            const int cib = lane & 3;
#pragma unroll
            for (int kc = 0; kc < 8; kc++) {
                const int ci0 = kc * 8 + cib;
                uint32_t bf[2][2];
                bf[0][0] = __float_as_uint(cache[ci0 * 132 + nb0]);
                bf[0][1] = __float_as_uint(cache[(ci0 + 4) * 132 + nb0]);
                bf[1][0] = __float_as_uint(cache[ci0 * 132 + nb0 + 8]);
                bf[1][1] = __float_as_uint(cache[(ci0 + 4) * 132 + nb0 + 8]);
#pragma unroll
                for (int ct = 0; ct < 8; ct++) {
                    float4 af = As[(kc * 8 + ct) * 32 + lane];
                    const uint32_t* a = (const uint32_t*)&af;
                    mma_tf32(d[ct][0], a, bf[0]);
                    mma_tf32(d[ct][1], a, bf[1]);
                }
            }
        }
    }
    __syncthreads();

    // epilogue: virtual rows v = ct*16+... (low) pair with v+64 at ct+4 (high),
    // both held by the SAME lane -> purely local select, float2 stores.
    const int r4 = lane >> 2;
    const int c2 = (lane & 3) * 2;
#pragma unroll
    for (int ct = 0; ct < 4; ct++) {
#pragma unroll
        for (int nt = 0; nt < 2; nt++) {
            const int n0 = w * 16 + nt * 8 + c2;
            const bool f0 = flg[n0] != 0;
            const bool f1 = flg[n0 + 1] != 0;
#pragma unroll
            for (int half = 0; half < 2; half++) {
                const int co = ct * 16 + r4 + half * 8;
                float v0 = f0 ? d[ct + 4][nt][half * 2]     : d[ct][nt][half * 2];
                float v1 = f1 ? d[ct + 4][nt][half * 2 + 1] : d[ct][nt][half * 2 + 1];
                *(float2*)&out[((b * COUT + co) * HH + h) * WW + w0 + n0] =
                    make_float2(v0, v1);
            }
        }
    }
}

// ---------------------------------------------------------------------------
extern "C" void kernel_launch(void* const* d_in, const int* in_sizes, int n_in,
                              void* d_out, int out_size)
{
    const float* x      = (const float*)d_in[0];
    const float* high_w = (const float*)d_in[1];
    const float* low1_w = (const float*)d_in[2];
    const float* low2_w = (const float*)d_in[3];
    const int* mask_idx = (const int*)d_in[4];
    const int* inv_idx  = (const int*)d_in[5];
    float* out = (float*)d_out;

    cudaFuncSetAttribute(conv_mma, cudaFuncAttributeMaxDynamicSharedMemorySize,
                         SMEM_TOTAL);

    prep_weights_mma<<<(9 * 8192 + 255) / 256, 256>>>(high_w, low1_w, low2_w);
    prep_flags<<<(NPIX + 255) / 256, 256>>>(mask_idx, inv_idx);
    conv_mma<<<4608, 256, SMEM_TOTAL>>>(x, out);
}

// round 14
// speedup vs baseline: 3.3127x; 1.4893x over previous
#include <cuda_runtime.h>
#include <cuda_bf16.h>
#include <cstdint>

#define HH 384
#define WW 384
#define BATCH 4
#define CIN 64
#define COUT 64
#define NPIX (BATCH*HH*WW)

// ---------------------------------------------------------------------------
// Scratch: A operand pre-baked in mma.m16n8k8 fragment order, tf32-rounded.
// Layout: g_amma[((tap*8 + kc)*8 + ct)*128 + lane*4 + j]
//   virtual row v = ct*16 + (lane>>2) + 8*(j&1);  ci = kc*8 + (lane&3) + 4*(j>>1)
//   rows v<64: W_low_eff(co=v), rows v>=64: W_high(co=v-64)
// ---------------------------------------------------------------------------
__device__ float g_amma[9 * 8192];
__device__ unsigned char g_flags[NPIX];

__device__ __forceinline__ float tf32_round(float v) {
    uint32_t t;
    asm("cvt.rna.tf32.f32 %0, %1;" : "=r"(t) : "f"(v));
    return __uint_as_float(t);
}

__device__ __forceinline__ uint32_t smem_u32(const void* p) {
    uint32_t a;
    asm("{ .reg .u64 t; cvta.to.shared.u64 t, %1; cvt.u32.u64 %0, t; }"
        : "=r"(a) : "l"(p));
    return a;
}

__device__ __forceinline__ void mma_tf32(float* d, const uint32_t* a,
                                         const uint32_t* b) {
    asm volatile(
        "mma.sync.aligned.m16n8k8.row.col.f32.tf32.tf32.f32 "
        "{%0,%1,%2,%3}, {%4,%5,%6,%7}, {%8,%9}, {%0,%1,%2,%3};"
        : "+f"(d[0]), "+f"(d[1]), "+f"(d[2]), "+f"(d[3])
        : "r"(a[0]), "r"(a[1]), "r"(a[2]), "r"(a[3]), "r"(b[0]), "r"(b[1]));
}

#define CP_ASYNC16(dst_u32, src_ptr) \
    asm volatile("cp.async.cg.shared.global [%0], [%1], 16;" \
                 :: "r"(dst_u32), "l"(src_ptr))
#define CP_COMMIT()  asm volatile("cp.async.commit_group;" ::: "memory")
#define CP_WAIT0()   asm volatile("cp.async.wait_group 0;" ::: "memory")

// ---------------------------------------------------------------------------
// Prep 1: weights -> fragment-ordered, tf32-rounded A images.
// ---------------------------------------------------------------------------
__global__ void prep_weights_mma(const float* __restrict__ high_w,  // (64,64,3,3)
                                 const float* __restrict__ low1_w,  // (16,64,3,3)
                                 const float* __restrict__ low2_w)  // (64,16,1,1)
{
    int id = blockIdx.x * blockDim.x + threadIdx.x;
    if (id >= 9 * 8192) return;
    int j    = id & 3;
    int lane = (id >> 2) & 31;
    int ct   = (id >> 7) & 7;
    int kc   = (id >> 10) & 7;
    int tap  = id >> 13;
    int v  = ct * 16 + (lane >> 2) + 8 * (j & 1);
    int ci = kc * 8 + (lane & 3) + 4 * (j >> 1);
    float val;
    if (v < 64) {
        float wle = 0.0f;
#pragma unroll
        for (int m = 0; m < 16; m++)
            wle += low2_w[v * 16 + m] * low1_w[(m * 64 + ci) * 9 + tap];
        val = wle;
    } else {
        val = high_w[((v - 64) * 64 + ci) * 9 + tap];
    }
    g_amma[id] = tf32_round(val);
}

// ---------------------------------------------------------------------------
// Prep 2: route flags.
// ---------------------------------------------------------------------------
__global__ void prep_flags(const int* __restrict__ mask_idx,
                           const int* __restrict__ inv_idx)
{
    int i = blockIdx.x * blockDim.x + threadIdx.x;
    if (i >= NPIX) return;
    if (i < NPIX / 2) g_flags[mask_idx[i]] = 1;
    else              g_flags[inv_idx[i - NPIX / 2]] = 0;
}

// ---------------------------------------------------------------------------
// Main: 128-pixel strip x 128 virtual couts, mma.sync tf32.
// 8 warps = (c = ct-half) x (p = pixel group of 32).
// Warp: 4 co-tiles x 4 n-tiles -> 64 acc regs; A frag reused 4x per load.
// A double-buffered via cp.async (tap t+1 streams during tap t compute).
// smem: [flags 128B][A0 32KB][A1 32KB][cache 64x132 f32 = 33792B] = 99456B
// ---------------------------------------------------------------------------
#define OFF_FLAGS 0
#define OFF_A0    128
#define OFF_A1    (128 + 32768)
#define OFF_CACHE (128 + 65536)
#define SMEM_TOTAL (OFF_CACHE + 64*132*4)   // 99456

__global__ __launch_bounds__(256, 2)
void conv_mma(const float* __restrict__ x, float* __restrict__ out)
{
    extern __shared__ char smem[];
    unsigned char* flg = (unsigned char*)(smem + OFF_FLAGS);
    float* cache = (float*)(smem + OFF_CACHE);          // [64][132] tf32-rounded
    const uint32_t sbase = smem_u32(smem);

    const int tid  = threadIdx.x;
    const int wrp  = tid >> 5;
    const int lane = tid & 31;
    const int c    = wrp >> 2;       // 0 = low-path couts, 1 = high-path
    const int p    = wrp & 3;        // pixel group (32 pixels)

    const int idx = blockIdx.x;
    const int b   = idx / 1152;
    const int rem = idx % 1152;
    const int h   = rem / 3;
    const int w0  = (rem % 3) * 128;

    if (tid < 128) flg[tid] = g_flags[(b * HH + h) * WW + w0 + tid];

    // prologue: prefetch A[tap 0] into buffer 0
    {
        const char* src = (const char*)g_amma;
        uint32_t dst = sbase + OFF_A0 + tid * 16;
#pragma unroll
        for (int i = 0; i < 8; i++)
            CP_ASYNC16(dst + i * 4096, src + tid * 16 + i * 4096);
        CP_COMMIT();
    }

    float d[4][4][4];
#pragma unroll
    for (int ct = 0; ct < 4; ct++)
#pragma unroll
        for (int nt = 0; nt < 4; nt++)
#pragma unroll
            for (int i = 0; i < 4; i++) d[ct][nt][i] = 0.0f;

    for (int kh = 0; kh < 3; kh++) {
        __syncthreads();                 // prior taps' cache reads complete
        const int rin = h + kh - 1;
        for (int i = tid; i < 64 * 132; i += 256) {
            int ci = i / 132, cc = i % 132;
            int g = w0 - 1 + cc;
            float v = 0.0f;
            if (rin >= 0 && rin < HH && g >= 0 && g < WW && cc < 130)
                v = x[((b * CIN + ci) * HH + rin) * WW + g];
            cache[i] = tf32_round(v);
        }

        for (int kw = 0; kw < 3; kw++) {
            const int tap = kh * 3 + kw;
            CP_WAIT0();                  // A[tap] landed
            __syncthreads();             // visibility + old-buffer reads done
            if (tap < 8) {               // prefetch A[tap+1] into other buffer
                const char* src = (const char*)(g_amma + (tap + 1) * 8192);
                uint32_t dst = sbase + (((tap + 1) & 1) ? OFF_A1 : OFF_A0)
                             + tid * 16;
#pragma unroll
                for (int i = 0; i < 8; i++)
                    CP_ASYNC16(dst + i * 4096, src + tid * 16 + i * 4096);
                CP_COMMIT();
            }
            const float4* As = (const float4*)(smem + ((tap & 1) ? OFF_A1 : OFF_A0));

            const int nb0 = p * 32 + (lane >> 2) + kw;  // cache col for nt=0
            const int cib = lane & 3;
#pragma unroll
            for (int kc = 0; kc < 8; kc++) {
                const int ci0 = kc * 8 + cib;
                uint32_t bf[4][2];
#pragma unroll
                for (int nt = 0; nt < 4; nt++) {
                    bf[nt][0] = __float_as_uint(cache[ci0 * 132 + nb0 + nt * 8]);
                    bf[nt][1] = __float_as_uint(cache[(ci0 + 4) * 132 + nb0 + nt * 8]);
                }
#pragma unroll
                for (int ctl = 0; ctl < 4; ctl++) {
                    float4 af = As[(kc * 8 + c * 4 + ctl) * 32 + lane];
                    const uint32_t* a = (const uint32_t*)&af;
                    mma_tf32(d[ctl][0], a, bf[0]);
                    mma_tf32(d[ctl][1], a, bf[1]);
                    mma_tf32(d[ctl][2], a, bf[2]);
                    mma_tf32(d[ctl][3], a, bf[3]);
                }
            }
        }
    }
    __syncthreads();                     // mainloop cache reads done

    // epilogue: predicated scatter into outbuf (reuse cache area).
    // warp c writes (co, n) where flag[n] == c -> each cell written once.
    const int r4 = lane >> 2;
    const int c2 = (lane & 3) * 2;
#pragma unroll
    for (int ctl = 0; ctl < 4; ctl++) {
#pragma unroll
        for (int nt = 0; nt < 4; nt++) {
            const int n0 = p * 32 + nt * 8 + c2;
            const bool f0 = ((int)flg[n0] == c);
            const bool f1 = ((int)flg[n0 + 1] == c);
#pragma unroll
            for (int half = 0; half < 2; half++) {
                const int co = ctl * 16 + r4 + half * 8;
                if (f0) cache[co * 132 + n0]     = d[ctl][nt][half * 2];
                if (f1) cache[co * 132 + n0 + 1] = d[ctl][nt][half * 2 + 1];
            }
        }
    }
    __syncthreads();

    // coalesced store: thread -> (co = tid>>2, quarter = tid&3), 32 floats
    {
        const int co = tid >> 2, q = tid & 3;
        float* orow = out + ((b * COUT + co) * HH + h) * WW + w0 + q * 32;
        const float* srow = cache + co * 132 + q * 32;
#pragma unroll
        for (int v = 0; v < 8; v++)
            *(float4*)(orow + v * 4) = *(const float4*)(srow + v * 4);
    }
}

// ---------------------------------------------------------------------------
extern "C" void kernel_launch(void* const* d_in, const int* in_sizes, int n_in,
                              void* d_out, int out_size)
{
    const float* x      = (const float*)d_in[0];
    const float* high_w = (const float*)d_in[1];
    const float* low1_w = (const float*)d_in[2];
    const float* low2_w = (const float*)d_in[3];
    const int* mask_idx = (const int*)d_in[4];
    const int* inv_idx  = (const int*)d_in[5];
    float* out = (float*)d_out;

    cudaFuncSetAttribute(conv_mma, cudaFuncAttributeMaxDynamicSharedMemorySize,
                         SMEM_TOTAL);

    prep_weights_mma<<<(9 * 8192 + 255) / 256, 256>>>(high_w, low1_w, low2_w);
    prep_flags<<<(NPIX + 255) / 256, 256>>>(mask_idx, inv_idx);
    conv_mma<<<4608, 256, SMEM_TOTAL>>>(x, out);
}

// round 15
// speedup vs baseline: 5.6861x; 1.7164x over previous
#include <cuda_runtime.h>
#include <cuda_fp16.h>
#include <cstdint>

#define HH 384
#define WW 384
#define BATCH 4
#define CIN 64
#define COUT 64
#define NPIX (BATCH*HH*WW)

// ---------------------------------------------------------------------------
// Scratch: A operand pre-baked as half2 in mma.m16n8k16 A-fragment order.
// u32 index = (((tap*4 + kc)*8 + ct)*32 + lane)*4 + j
//   row v = ct*16 + (lane>>2) + 8*(j&1)
//   k pair = (lane&3)*2 + 8*(j>>1) + {0,1};  ci = kc*16 + k
//   rows v<64: W_low_eff(co=v), v>=64: W_high(co=v-64)
// ---------------------------------------------------------------------------
__device__ uint32_t g_ahalf[9 * 4096];
__device__ unsigned char g_flags[NPIX];

__device__ __forceinline__ uint32_t smem_u32(const void* p) {
    uint32_t a;
    asm("{ .reg .u64 t; cvta.to.shared.u64 t, %1; cvt.u32.u64 %0, t; }"
        : "=r"(a) : "l"(p));
    return a;
}

__device__ __forceinline__ void mma_f16(float* d, const uint32_t* a,
                                        const uint32_t* b) {
    asm volatile(
        "mma.sync.aligned.m16n8k16.row.col.f32.f16.f16.f32 "
        "{%0,%1,%2,%3}, {%4,%5,%6,%7}, {%8,%9}, {%0,%1,%2,%3};"
        : "+f"(d[0]), "+f"(d[1]), "+f"(d[2]), "+f"(d[3])
        : "r"(a[0]), "r"(a[1]), "r"(a[2]), "r"(a[3]), "r"(b[0]), "r"(b[1]));
}

#define CP_ASYNC16(dst_u32, src_ptr) \
    asm volatile("cp.async.cg.shared.global [%0], [%1], 16;" \
                 :: "r"(dst_u32), "l"(src_ptr))
#define CP_COMMIT()  asm volatile("cp.async.commit_group;" ::: "memory")
#define CP_WAIT0()   asm volatile("cp.async.wait_group 0;" ::: "memory")

// ---------------------------------------------------------------------------
// Prep 1: weights -> fp16 fragment-ordered A images.
// ---------------------------------------------------------------------------
__global__ void prep_weights_f16(const float* __restrict__ high_w,  // (64,64,3,3)
                                 const float* __restrict__ low1_w,  // (16,64,3,3)
                                 const float* __restrict__ low2_w)  // (64,16,1,1)
{
    int id = blockIdx.x * blockDim.x + threadIdx.x;
    if (id >= 9 * 4096) return;
    int j    = id & 3;
    int lane = (id >> 2) & 31;
    int ct   = (id >> 7) & 7;
    int kc   = (id >> 10) & 3;
    int tap  = id >> 12;
    int v  = ct * 16 + (lane >> 2) + 8 * (j & 1);
    int kb = (lane & 3) * 2 + 8 * (j >> 1);
    float w01[2];
#pragma unroll
    for (int e = 0; e < 2; e++) {
        int ci = kc * 16 + kb + e;
        if (v < 64) {
            float wle = 0.0f;
#pragma unroll
            for (int m = 0; m < 16; m++)
                wle += low2_w[v * 16 + m] * low1_w[(m * 64 + ci) * 9 + tap];
            w01[e] = wle;
        } else {
            w01[e] = high_w[((v - 64) * 64 + ci) * 9 + tap];
        }
    }
    __half2 h = __floats2half2_rn(w01[0], w01[1]);
    g_ahalf[id] = *(const uint32_t*)&h;
}

// ---------------------------------------------------------------------------
// Prep 2: route flags.
// ---------------------------------------------------------------------------
__global__ void prep_flags(const int* __restrict__ mask_idx,
                           const int* __restrict__ inv_idx)
{
    int i = blockIdx.x * blockDim.x + threadIdx.x;
    if (i >= NPIX) return;
    if (i < NPIX / 2) g_flags[mask_idx[i]] = 1;
    else              g_flags[inv_idx[i - NPIX / 2]] = 0;
}

// ---------------------------------------------------------------------------
// Main: 128-pixel strip x 128 virtual couts, mma.sync fp16 m16n8k16.
// 8 warps = (c = ct-half) x (p = pixel group of 32); warp: 4 co x 4 n tiles.
// A double-buffered via cp.async; x cache as half2 (ci, ci+1) pairs,
// row stride 136 u32 -> conflict-free b-fragment loads.
// smem: [flags 128][A0 16K][A1 16K][cache2 32x136 u32 = 17408][outbuf 64x132 f32]
// ---------------------------------------------------------------------------
#define OFF_FLAGS 0
#define OFF_A0    128
#define OFF_A1    (128 + 16384)
#define OFF_CH    (128 + 32768)
#define OFF_OUT   (OFF_CH + 32*136*4)
#define SMEM_TOTAL (OFF_OUT + 64*132*4)   // 84096

__global__ __launch_bounds__(256, 2)
void conv_mma(const float* __restrict__ x, float* __restrict__ out)
{
    extern __shared__ char smem[];
    unsigned char* flg = (unsigned char*)(smem + OFF_FLAGS);
    uint32_t* cache2 = (uint32_t*)(smem + OFF_CH);      // [32][136] half2 pairs
    float* obuf = (float*)(smem + OFF_OUT);             // [64][132]
    const uint32_t sbase = smem_u32(smem);

    const int tid  = threadIdx.x;
    const int wrp  = tid >> 5;
    const int lane = tid & 31;
    const int c    = wrp >> 2;       // 0 = low-path couts, 1 = high-path
    const int p    = wrp & 3;        // pixel group (32 pixels)

    const int idx = blockIdx.x;
    const int b   = idx / 1152;
    const int rem = idx % 1152;
    const int h   = rem / 3;
    const int w0  = (rem % 3) * 128;

    if (tid < 128) flg[tid] = g_flags[(b * HH + h) * WW + w0 + tid];

    // prologue: prefetch A[tap 0] (16 KB = 1024 x 16B)
    {
        const char* src = (const char*)g_ahalf;
        uint32_t dst = sbase + OFF_A0 + tid * 16;
#pragma unroll
        for (int i = 0; i < 4; i++)
            CP_ASYNC16(dst + i * 4096, src + tid * 16 + i * 4096);
        CP_COMMIT();
    }

    float d[4][4][4];
#pragma unroll
    for (int ct = 0; ct < 4; ct++)
#pragma unroll
        for (int nt = 0; nt < 4; nt++)
#pragma unroll
            for (int i = 0; i < 4; i++) d[ct][nt][i] = 0.0f;

    for (int kh = 0; kh < 3; kh++) {
        __syncthreads();                 // prior taps' cache reads complete
        const int rin = h + kh - 1;
        const bool rok = (rin >= 0 && rin < HH);
        for (int i = tid; i < 32 * 136; i += 256) {
            int cp = i / 136, cc = i % 136;
            int g = w0 - 1 + cc;
            float v0 = 0.0f, v1 = 0.0f;
            if (rok && g >= 0 && g < WW && cc < 130) {
                const float* base = x + ((b * CIN + cp * 2) * HH + rin) * WW + g;
                v0 = base[0];
                v1 = base[HH * WW];
            }
            __half2 hv = __floats2half2_rn(v0, v1);
            cache2[i] = *(const uint32_t*)&hv;
        }

        for (int kw = 0; kw < 3; kw++) {
            const int tap = kh * 3 + kw;
            CP_WAIT0();                  // A[tap] landed
            __syncthreads();             // visibility + old-buffer reads done
            if (tap < 8) {               // prefetch A[tap+1]
                const char* src = (const char*)(g_ahalf + (tap + 1) * 4096);
                uint32_t dst = sbase + (((tap + 1) & 1) ? OFF_A1 : OFF_A0)
                             + tid * 16;
#pragma unroll
                for (int i = 0; i < 4; i++)
                    CP_ASYNC16(dst + i * 4096, src + tid * 16 + i * 4096);
                CP_COMMIT();
            }
            const uint4* As = (const uint4*)(smem + ((tap & 1) ? OFF_A1 : OFF_A0));

            const int nb0 = p * 32 + (lane >> 2) + kw;  // cache col for nt=0
            const int tg  = lane & 3;
#pragma unroll
            for (int kc = 0; kc < 4; kc++) {
                const int cp0 = kc * 8 + tg;
                uint32_t bf[4][2];
#pragma unroll
                for (int nt = 0; nt < 4; nt++) {
                    bf[nt][0] = cache2[cp0 * 136 + nb0 + nt * 8];
                    bf[nt][1] = cache2[(cp0 + 4) * 136 + nb0 + nt * 8];
                }
#pragma unroll
                for (int ctl = 0; ctl < 4; ctl++) {
                    uint4 af = As[(kc * 8 + c * 4 + ctl) * 32 + lane];
                    const uint32_t* a = (const uint32_t*)&af;
                    mma_f16(d[ctl][0], a, bf[0]);
                    mma_f16(d[ctl][1], a, bf[1]);
                    mma_f16(d[ctl][2], a, bf[2]);
                    mma_f16(d[ctl][3], a, bf[3]);
                }
            }
        }
    }
    __syncthreads();                     // mainloop cache reads done

    // epilogue: predicated scatter; warp c writes cells where flag == c.
    const int r4 = lane >> 2;
    const int c2 = (lane & 3) * 2;
#pragma unroll
    for (int ctl = 0; ctl < 4; ctl++) {
#pragma unroll
        for (int nt = 0; nt < 4; nt++) {
            const int n0 = p * 32 + nt * 8 + c2;
            const bool f0 = ((int)flg[n0] == c);
            const bool f1 = ((int)flg[n0 + 1] == c);
#pragma unroll
            for (int half = 0; half < 2; half++) {
                const int co = ctl * 16 + r4 + half * 8;
                if (f0) obuf[co * 132 + n0]     = d[ctl][nt][half * 2];
                if (f1) obuf[co * 132 + n0 + 1] = d[ctl][nt][half * 2 + 1];
            }
        }
    }
    __syncthreads();

    // coalesced store: thread -> (co = tid>>2, quarter = tid&3), 32 floats
    {
        const int co = tid >> 2, q = tid & 3;
        float* orow = out + ((b * COUT + co) * HH + h) * WW + w0 + q * 32;
        const float* srow = obuf + co * 132 + q * 32;
#pragma unroll
        for (int v = 0; v < 8; v++)
            *(float4*)(orow + v * 4) = *(const float4*)(srow + v * 4);
    }
}

// ---------------------------------------------------------------------------
extern "C" void kernel_launch(void* const* d_in, const int* in_sizes, int n_in,
                              void* d_out, int out_size)
{
    const float* x      = (const float*)d_in[0];
    const float* high_w = (const float*)d_in[1];
    const float* low1_w = (const float*)d_in[2];
    const float* low2_w = (const float*)d_in[3];
    const int* mask_idx = (const int*)d_in[4];
    const int* inv_idx  = (const int*)d_in[5];
    float* out = (float*)d_out;

    cudaFuncSetAttribute(conv_mma, cudaFuncAttributeMaxDynamicSharedMemorySize,
                         SMEM_TOTAL);

    prep_weights_f16<<<(9 * 4096 + 255) / 256, 256>>>(high_w, low1_w, low2_w);
    prep_flags<<<(NPIX + 255) / 256, 256>>>(mask_idx, inv_idx);
    conv_mma<<<4608, 256, SMEM_TOTAL>>>(x, out);
}